// round 15
// baseline (speedup 1.0000x reference)
#include <cuda_runtime.h>
#include <cstdint>

#define N_NODES 50000
#define N_EDGES 800000
#define NUM_GRAPHS 256
#define IN_DIM 128
#define H_DIM 64
#define HID 256
#define EPS 1e-5f

#define SCAN_B 1024
#define SCAN_NB ((N_NODES + SCAN_B - 1) / SCAN_B)   // 49

// ---------------- scratch (static device memory; no allocation) ----------------
__device__ int   g_src[N_EDGES];
__device__ int   g_dst[N_EDGES];
__device__ int   g_batch[N_NODES];
__device__ int   g_deg[N_NODES];
__device__ int   g_off[N_NODES];
__device__ int   g_cur[N_NODES];
__device__ int   g_csr[N_EDGES];
__device__ int   g_bsum[SCAN_NB];
__device__ int   g_boff[SCAN_NB];
__device__ float g_yl[N_NODES * H_DIM];
__device__ float g_yr[N_NODES * H_DIM];
__device__ float g_hA[N_NODES * H_DIM];
__device__ float g_hB[N_NODES * H_DIM];
__device__ float g_pool[NUM_GRAPHS * H_DIM];
__device__ float g_pcnt[NUM_GRAPHS];
__device__ float g_m1[NUM_GRAPHS * HID];
__device__ float g_m2[NUM_GRAPHS * (HID / 2)];
__device__ float g_m3[NUM_GRAPHS * (HID / 4)];

__device__ __forceinline__ float* buf_by_id(int id) {
    switch (id) {
        case 0: return g_yl;
        case 1: return g_yr;
        case 2: return g_hA;
        case 3: return g_hB;
        default: return g_pool;
    }
}

// Per-block int64 detection from the EDGE buffer: read first 256 int64 slots.
__device__ __forceinline__ int detect_is64(const long long* __restrict__ e,
                                           int* s_flag) {
    int t = threadIdx.x;
    if (t == 0) *s_flag = 1;
    __syncthreads();
    if (t < 256) {
        long long v = e[t];
        if (v < 0 || v >= (long long)N_NODES) *s_flag = 0;
    }
    __syncthreads();
    return *s_flag;
}

// ---------------- zero scratch (must precede convert_edges histogram) ----------
__global__ void zero_kernel() {
    int i = blockIdx.x * blockDim.x + threadIdx.x;
    if (i < N_NODES) g_deg[i] = 0;
    if (i < NUM_GRAPHS * H_DIM) g_pool[i] = 0.0f;
    if (i < NUM_GRAPHS) g_pcnt[i] = 0.0f;
}

// convert + degree histogram fused; local dtype detection
__global__ void convert_edges(const void* __restrict__ e) {
    __shared__ int s_flag;
    int is64 = detect_is64((const long long*)e, &s_flag);
    int i = blockIdx.x * blockDim.x + threadIdx.x;
    if (i >= N_EDGES) return;
    int s, d;
    if (is64) {
        const long long* p = (const long long*)e;
        s = (int)p[i];
        d = (int)p[N_EDGES + i];
    } else {
        const int* p = (const int*)e;
        s = p[i];
        d = p[N_EDGES + i];
    }
    g_src[i] = s;
    g_dst[i] = d;
    atomicAdd(&g_deg[d], 1);
}

__global__ void convert_batch(const void* __restrict__ bptr,
                              const void* __restrict__ e) {
    __shared__ int s_flag;
    int is64 = detect_is64((const long long*)e, &s_flag);
    int i = blockIdx.x * blockDim.x + threadIdx.x;
    if (i >= N_NODES) return;
    if (is64) g_batch[i] = (int)((const long long*)bptr)[i];
    else      g_batch[i] = ((const int*)bptr)[i];
}

// ---------------- CSR build: multi-block scan (49 blocks x 1024) --------------
__global__ void blocksum_kernel() {
    __shared__ int s[SCAN_B];
    int t = threadIdx.x;
    int i = blockIdx.x * SCAN_B + t;
    s[t] = (i < N_NODES) ? g_deg[i] : 0;
    __syncthreads();
    for (int st = SCAN_B / 2; st > 0; st >>= 1) {
        if (t < st) s[t] += s[t + st];
        __syncthreads();
    }
    if (t == 0) g_bsum[blockIdx.x] = s[0];
}

__global__ void scan_bsum_kernel() {
    __shared__ int s[64];
    int t = threadIdx.x;
    int v = (t < SCAN_NB) ? g_bsum[t] : 0;
    s[t] = v;
    __syncthreads();
    for (int off = 1; off < 64; off <<= 1) {
        int x = (t >= off) ? s[t - off] : 0;
        __syncthreads();
        s[t] += x;
        __syncthreads();
    }
    if (t < SCAN_NB) g_boff[t] = s[t] - v;  // exclusive
}

__global__ void block_scan_kernel() {
    __shared__ int s[SCAN_B];
    int t = threadIdx.x;
    int i = blockIdx.x * SCAN_B + t;
    int v = (i < N_NODES) ? g_deg[i] : 0;
    s[t] = v;
    __syncthreads();
    for (int off = 1; off < SCAN_B; off <<= 1) {
        int x = (t >= off) ? s[t - off] : 0;
        __syncthreads();
        s[t] += x;
        __syncthreads();
    }
    if (i < N_NODES) {
        int o = g_boff[blockIdx.x] + s[t] - v;  // exclusive
        g_off[i] = o;
        g_cur[i] = o;
    }
}

__global__ void fill_kernel() {
    int i = blockIdx.x * blockDim.x + threadIdx.x;
    if (i < N_EDGES) {
        int p = atomicAdd(&g_cur[g_dst[i]], 1);
        g_csr[p] = g_src[i];
    }
}

// ---------------- tensor-core dual GEMM (TF32 mma.sync) ----------------------
// yl = in @ Wl, yr = in @ Wr + bias.  Nout = 64.  K in {128, 64}.
// 256 threads = 8 warps; each warp computes a 16-row stripe x 64 cols x 2 mats.
// m16n8k8 fragments loaded directly from global (W stays hot in L1).

__device__ __forceinline__ uint32_t tf32_of(float x) {
    uint32_t r;
    asm("cvt.rna.tf32.f32 %0, %1;" : "=r"(r) : "f"(x));
    return r;
}

__device__ __forceinline__ void mma_tf32(float* c,
                                         uint32_t a0, uint32_t a1,
                                         uint32_t a2, uint32_t a3,
                                         uint32_t b0, uint32_t b1) {
    asm volatile(
        "mma.sync.aligned.m16n8k8.row.col.f32.tf32.tf32.f32 "
        "{%0,%1,%2,%3}, {%4,%5,%6,%7}, {%8,%9}, {%0,%1,%2,%3};\n"
        : "+f"(c[0]), "+f"(c[1]), "+f"(c[2]), "+f"(c[3])
        : "r"(a0), "r"(a1), "r"(a2), "r"(a3), "r"(b0), "r"(b1));
}

__global__ __launch_bounds__(256)
void gemm_dual_tc(const float* __restrict__ xin, int in_id,
                  const float* __restrict__ Wl,
                  const float* __restrict__ bias,
                  const float* __restrict__ Wr, int K) {
    const float* in = (in_id < 0) ? xin : buf_by_id(in_id);
    const int M = N_NODES;

    int lane = threadIdx.x & 31;
    int warp = threadIdx.x >> 5;
    int kq = lane & 3;       // 0..3 : k within fragment / col pair at store
    int lg = lane >> 2;      // 0..7 : row in group / n within block
    int r0 = blockIdx.x * 128 + warp * 16 + lg;
    int r1 = r0 + 8;
    bool v0 = r0 < M, v1 = r1 < M;

    float accL[8][4];
    float accR[8][4];
#pragma unroll
    for (int j = 0; j < 8; j++)
#pragma unroll
        for (int c = 0; c < 4; c++) { accL[j][c] = 0.0f; accR[j][c] = 0.0f; }

    const float* rowp0 = in + (size_t)(v0 ? r0 : 0) * K;
    const float* rowp1 = in + (size_t)(v1 ? r1 : 0) * K;

    for (int kc = 0; kc < K; kc += 8) {
        float x0 = v0 ? rowp0[kc + kq] : 0.0f;
        float x1 = v1 ? rowp1[kc + kq] : 0.0f;
        float x2 = v0 ? rowp0[kc + kq + 4] : 0.0f;
        float x3 = v1 ? rowp1[kc + kq + 4] : 0.0f;
        uint32_t a0 = tf32_of(x0);
        uint32_t a1 = tf32_of(x1);
        uint32_t a2 = tf32_of(x2);
        uint32_t a3 = tf32_of(x3);

        const float* w0l = Wl + (size_t)(kc + kq) * 64 + lg;
        const float* w1l = w0l + 4 * 64;
        const float* w0r = Wr + (size_t)(kc + kq) * 64 + lg;
        const float* w1r = w0r + 4 * 64;

#pragma unroll
        for (int j = 0; j < 8; j++) {
            uint32_t bl0 = tf32_of(__ldg(w0l + j * 8));
            uint32_t bl1 = tf32_of(__ldg(w1l + j * 8));
            mma_tf32(accL[j], a0, a1, a2, a3, bl0, bl1);
            uint32_t br0 = tf32_of(__ldg(w0r + j * 8));
            uint32_t br1 = tf32_of(__ldg(w1r + j * 8));
            mma_tf32(accR[j], a0, a1, a2, a3, br0, br1);
        }
    }

    // store: c0/c1 -> (r0, col, col+1); c2/c3 -> (r1, col, col+1)
    int colb = 2 * kq;
#pragma unroll
    for (int j = 0; j < 8; j++) {
        int c = j * 8 + colb;
        float bx = bias[c], by = bias[c + 1];
        if (v0) {
            *(float2*)(g_yl + (size_t)r0 * 64 + c) = make_float2(accL[j][0], accL[j][1]);
            *(float2*)(g_yr + (size_t)r0 * 64 + c) = make_float2(accR[j][0] + bx, accR[j][1] + by);
        }
        if (v1) {
            *(float2*)(g_yl + (size_t)r1 * 64 + c) = make_float2(accL[j][2], accL[j][3]);
            *(float2*)(g_yr + (size_t)r1 * 64 + c) = make_float2(accR[j][2] + bx, accR[j][3] + by);
        }
    }
}

// ---------------- aggregation: out[n] = mean_{e in CSR(n)} yl[src_e] + yr[n] ----
__global__ __launch_bounds__(256)
void aggregate_kernel(int out_id) {
    float* out = buf_by_id(out_id);
    int tid = blockIdx.x * blockDim.x + threadIdx.x;
    int node = tid >> 4;             // 16 threads per node
    int lane = threadIdx.x & 15;     // covers 64 floats as float4
    if (node >= N_NODES) return;
    int start = g_off[node];
    int d = g_deg[node];

    float4 a = make_float4(0.f, 0.f, 0.f, 0.f);
    const int* csr = g_csr + start;
    int e = 0;
    for (; e + 4 <= d; e += 4) {
        int s0 = csr[e + 0];
        int s1 = csr[e + 1];
        int s2 = csr[e + 2];
        int s3 = csr[e + 3];
        float4 v0 = *(const float4*)(g_yl + (size_t)s0 * 64 + lane * 4);
        float4 v1 = *(const float4*)(g_yl + (size_t)s1 * 64 + lane * 4);
        float4 v2 = *(const float4*)(g_yl + (size_t)s2 * 64 + lane * 4);
        float4 v3 = *(const float4*)(g_yl + (size_t)s3 * 64 + lane * 4);
        a.x += v0.x + v1.x + v2.x + v3.x;
        a.y += v0.y + v1.y + v2.y + v3.y;
        a.z += v0.z + v1.z + v2.z + v3.z;
        a.w += v0.w + v1.w + v2.w + v3.w;
    }
    for (; e < d; e++) {
        int s = csr[e];
        float4 v = *(const float4*)(g_yl + (size_t)s * 64 + lane * 4);
        a.x += v.x; a.y += v.y; a.z += v.z; a.w += v.w;
    }
    float inv = (d > 0) ? (1.0f / (float)d) : 0.0f;
    float4 r = *(const float4*)(g_yr + (size_t)node * 64 + lane * 4);
    float4 o;
    o.x = a.x * inv + r.x;
    o.y = a.y * inv + r.y;
    o.z = a.z * inv + r.z;
    o.w = a.w * inv + r.w;
    *(float4*)(out + (size_t)node * 64 + lane * 4) = o;
}

// ---------------- global mean pool (batch sorted) ----------------
__global__ void pool_kernel(int in_id) {
    const float* h = buf_by_id(in_id);
    int f = threadIdx.x & 63;
    int sub = threadIdx.x >> 6;
    int base = blockIdx.x * 128 + sub * 32;
    if (base >= N_NODES) return;
    int end = base + 32;
    if (end > N_NODES) end = N_NODES;
    float run = 0.0f, cnt = 0.0f;
    int cur = -1;
    for (int n = base; n < end; n++) {
        int b = g_batch[n];
        if (b != cur) {
            if (cur >= 0) {
                atomicAdd(&g_pool[cur * 64 + f], run);
                if (f == 0) atomicAdd(&g_pcnt[cur], cnt);
            }
            run = 0.0f; cnt = 0.0f; cur = b;
        }
        run += h[(size_t)n * 64 + f];
        cnt += 1.0f;
    }
    if (cur >= 0) {
        atomicAdd(&g_pool[cur * 64 + f], run);
        if (f == 0) atomicAdd(&g_pcnt[cur], cnt);
    }
}

// ---------------- MLP head ----------------
__global__ void mlp_gemm(int stage, const float* __restrict__ W,
                         const float* __restrict__ b, float* __restrict__ ext_out,
                         int K, int Nout) {
    const float* in;
    float* out;
    switch (stage) {
        case 0: in = g_pool; out = g_m1; break;
        case 1: in = g_m1;   out = g_m2; break;
        case 2: in = g_m2;   out = g_m3; break;
        default: in = g_m3;  out = ext_out; break;
    }
    int idx = blockIdx.x * blockDim.x + threadIdx.x;
    if (idx >= NUM_GRAPHS * Nout) return;
    int r = idx / Nout;
    int j = idx - r * Nout;
    float acc = 0.0f;
    const float* ir = in + (size_t)r * K;
    for (int k = 0; k < K; k++) acc += ir[k] * W[(size_t)k * Nout + j];
    if (stage == 0) acc *= 1.0f / fmaxf(g_pcnt[r], 1.0f);
    out[idx] = acc + b[j];
}

// one block per column; blockDim = NUM_GRAPHS = 256
__global__ void bn_tanh_kernel(int which, const float* __restrict__ g,
                               const float* __restrict__ be, int ncols) {
    float* y = (which == 0) ? g_m1 : (which == 1) ? g_m2 : g_m3;
    __shared__ float sd[256];
    __shared__ float sm[2];
    int j = blockIdx.x;
    int t = threadIdx.x;
    float v = y[(size_t)t * ncols + j];
    sd[t] = v;
    __syncthreads();
    for (int s = 128; s > 0; s >>= 1) {
        if (t < s) sd[t] += sd[t + s];
        __syncthreads();
    }
    if (t == 0) sm[0] = sd[0] * (1.0f / NUM_GRAPHS);
    __syncthreads();
    float mean = sm[0];
    float d = v - mean;
    sd[t] = d * d;
    __syncthreads();
    for (int s = 128; s > 0; s >>= 1) {
        if (t < s) sd[t] += sd[t + s];
        __syncthreads();
    }
    if (t == 0) sm[1] = sd[0] * (1.0f / NUM_GRAPHS);
    __syncthreads();
    float var = sm[1];
    float o = d * rsqrtf(var + EPS) * g[j] + be[j];
    y[(size_t)t * ncols + j] = tanhf(o);
}

// ---------------- launch ----------------
extern "C" void kernel_launch(void* const* d_in, const int* in_sizes, int n_in,
                              void* d_out, int out_size) {
    const float* x     = (const float*)d_in[0];
    const void*  eidx  = d_in[1];
    const void*  batch = d_in[2];
    const float* W1l = (const float*)d_in[3];
    const float* b1l = (const float*)d_in[4];
    const float* W1r = (const float*)d_in[5];
    const float* W2l = (const float*)d_in[6];
    const float* b2l = (const float*)d_in[7];
    const float* W2r = (const float*)d_in[8];
    const float* W3l = (const float*)d_in[9];
    const float* b3l = (const float*)d_in[10];
    const float* W3r = (const float*)d_in[11];
    const float* lin1_w = (const float*)d_in[12];
    const float* lin1_b = (const float*)d_in[13];
    const float* g1  = (const float*)d_in[14];
    const float* be1 = (const float*)d_in[15];
    const float* lin2_w = (const float*)d_in[16];
    const float* lin2_b = (const float*)d_in[17];
    const float* g2  = (const float*)d_in[18];
    const float* be2 = (const float*)d_in[19];
    const float* lin3_w = (const float*)d_in[20];
    const float* lin3_b = (const float*)d_in[21];
    const float* g3  = (const float*)d_in[22];
    const float* be3 = (const float*)d_in[23];
    const float* lin4_w = (const float*)d_in[24];
    const float* lin4_b = (const float*)d_in[25];
    float* out = (float*)d_out;

    const int EB = (N_EDGES + 255) / 256;        // 3125
    const int NBn = (N_NODES + 255) / 256;       // 196
    const int GB = (N_NODES + 127) / 128;        // 391 (128 rows per block)
    const int AB = (N_NODES * 16 + 255) / 256;   // 3125 (16 threads/node)

    // zero BEFORE convert (fused degree histogram)
    zero_kernel<<<NBn, 256>>>();
    convert_edges<<<EB, 256>>>(eidx);
    convert_batch<<<NBn, 256>>>(batch, eidx);

    // CSR build (multi-block scan)
    blocksum_kernel<<<SCAN_NB, SCAN_B>>>();
    scan_bsum_kernel<<<1, 64>>>();
    block_scan_kernel<<<SCAN_NB, SCAN_B>>>();
    fill_kernel<<<EB, 256>>>();

    // Layer 1: linear-first (tensor core), then aggregate (hA = buf 2, hB = buf 3)
    gemm_dual_tc<<<GB, 256>>>(x, -1, W1l, b1l, W1r, IN_DIM);
    aggregate_kernel<<<AB, 256>>>(2);
    // Layer 2
    gemm_dual_tc<<<GB, 256>>>(nullptr, 2, W2l, b2l, W2r, H_DIM);
    aggregate_kernel<<<AB, 256>>>(3);
    // Layer 3
    gemm_dual_tc<<<GB, 256>>>(nullptr, 3, W3l, b3l, W3r, H_DIM);
    aggregate_kernel<<<AB, 256>>>(2);

    // global mean pool (division folded into mlp stage 0)
    pool_kernel<<<GB, 256>>>(2);

    // MLP head (kept fp32-exact)
    mlp_gemm<<<(NUM_GRAPHS * HID + 255) / 256, 256>>>(0, lin1_w, lin1_b, nullptr,
                                                      H_DIM, HID);
    bn_tanh_kernel<<<HID, 256>>>(0, g1, be1, HID);
    mlp_gemm<<<(NUM_GRAPHS * (HID / 2) + 255) / 256, 256>>>(1, lin2_w, lin2_b, nullptr,
                                                            HID, HID / 2);
    bn_tanh_kernel<<<HID / 2, 256>>>(1, g2, be2, HID / 2);
    mlp_gemm<<<(NUM_GRAPHS * (HID / 4) + 255) / 256, 256>>>(2, lin3_w, lin3_b, nullptr,
                                                            HID / 2, HID / 4);
    bn_tanh_kernel<<<HID / 4, 256>>>(2, g3, be3, HID / 4);
    mlp_gemm<<<(NUM_GRAPHS * 10 + 255) / 256, 256>>>(3, lin4_w, lin4_b, out,
                                                     HID / 4, 10);
}

// round 16
// speedup vs baseline: 1.2288x; 1.2288x over previous
#include <cuda_runtime.h>
#include <cstdint>

#define N_NODES 50000
#define N_EDGES 800000
#define NUM_GRAPHS 256
#define IN_DIM 128
#define H_DIM 64
#define HID 256
#define EPS 1e-5f

#define SCAN_B 1024
#define SCAN_NB ((N_NODES + SCAN_B - 1) / SCAN_B)   // 49

// ---------------- scratch (static device memory; no allocation) ----------------
__device__ int   g_src[N_EDGES];
__device__ int   g_dst[N_EDGES];
__device__ int   g_batch[N_NODES];
__device__ int   g_deg[N_NODES];
__device__ int   g_off[N_NODES];
__device__ int   g_cur[N_NODES];
__device__ int   g_csr[N_EDGES];
__device__ int   g_bsum[SCAN_NB];
__device__ float g_yl[N_NODES * H_DIM];
__device__ float g_yr[N_NODES * H_DIM];
__device__ float g_hA[N_NODES * H_DIM];
__device__ float g_hB[N_NODES * H_DIM];
__device__ float g_pool[NUM_GRAPHS * H_DIM];
__device__ float g_pcnt[NUM_GRAPHS];
__device__ float g_m1[NUM_GRAPHS * HID];
__device__ float g_m2[NUM_GRAPHS * (HID / 2)];
__device__ float g_m3[NUM_GRAPHS * (HID / 4)];

__device__ __forceinline__ float* buf_by_id(int id) {
    switch (id) {
        case 0: return g_yl;
        case 1: return g_yr;
        case 2: return g_hA;
        case 3: return g_hB;
        default: return g_pool;
    }
}

// ---------------- packed f32x2 helpers (sm_103a FFMA2 path) -------------------
__device__ __forceinline__ unsigned long long pk2(float x, float y) {
    unsigned long long r;
    asm("mov.b64 %0, {%1, %2};" : "=l"(r) : "f"(x), "f"(y));
    return r;
}
__device__ __forceinline__ unsigned long long spl2(float x) {
    unsigned long long r;
    asm("mov.b64 %0, {%1, %1};" : "=l"(r) : "f"(x));
    return r;
}
__device__ __forceinline__ void fma2(unsigned long long& c,
                                     unsigned long long a,
                                     unsigned long long b) {
    asm("fma.rn.f32x2 %0, %1, %2, %3;" : "=l"(c) : "l"(a), "l"(b), "l"(c));
}
__device__ __forceinline__ float2 upk2(unsigned long long v) {
    float2 r;
    asm("mov.b64 {%0, %1}, %2;" : "=f"(r.x), "=f"(r.y) : "l"(v));
    return r;
}

// Per-block int64 detection from the EDGE buffer: read first 256 int64 slots.
__device__ __forceinline__ int detect_is64(const long long* __restrict__ e,
                                           int* s_flag) {
    int t = threadIdx.x;
    if (t == 0) *s_flag = 1;
    __syncthreads();
    if (t < 256) {
        long long v = e[t];
        if (v < 0 || v >= (long long)N_NODES) *s_flag = 0;
    }
    __syncthreads();
    return *s_flag;
}

// ---------------- zero scratch (must precede convert_edges histogram) ----------
__global__ void zero_kernel() {
    int i = blockIdx.x * blockDim.x + threadIdx.x;
    if (i < N_NODES) g_deg[i] = 0;
    if (i < NUM_GRAPHS * H_DIM) g_pool[i] = 0.0f;
    if (i < NUM_GRAPHS) g_pcnt[i] = 0.0f;
}

// convert + degree histogram fused; local dtype detection
__global__ void convert_edges(const void* __restrict__ e) {
    __shared__ int s_flag;
    int is64 = detect_is64((const long long*)e, &s_flag);
    int i = blockIdx.x * blockDim.x + threadIdx.x;
    if (i >= N_EDGES) return;
    int s, d;
    if (is64) {
        const long long* p = (const long long*)e;
        s = (int)p[i];
        d = (int)p[N_EDGES + i];
    } else {
        const int* p = (const int*)e;
        s = p[i];
        d = p[N_EDGES + i];
    }
    g_src[i] = s;
    g_dst[i] = d;
    atomicAdd(&g_deg[d], 1);
}

__global__ void convert_batch(const void* __restrict__ bptr,
                              const void* __restrict__ e) {
    __shared__ int s_flag;
    int is64 = detect_is64((const long long*)e, &s_flag);
    int i = blockIdx.x * blockDim.x + threadIdx.x;
    if (i >= N_NODES) return;
    if (is64) g_batch[i] = (int)((const long long*)bptr)[i];
    else      g_batch[i] = ((const int*)bptr)[i];
}

// ---------------- CSR build: blocksum + fused block_scan ----------------------
__global__ void blocksum_kernel() {
    __shared__ int s[SCAN_B];
    int t = threadIdx.x;
    int i = blockIdx.x * SCAN_B + t;
    s[t] = (i < N_NODES) ? g_deg[i] : 0;
    __syncthreads();
    for (int st = SCAN_B / 2; st > 0; st >>= 1) {
        if (t < st) s[t] += s[t + st];
        __syncthreads();
    }
    if (t == 0) g_bsum[blockIdx.x] = s[0];
}

// block_scan with the cross-block offset computed locally (scan_bsum fused):
// threads 0..63 load bsums of preceding blocks, tree-reduce to one offset.
__global__ void block_scan_kernel() {
    __shared__ int s[SCAN_B];
    __shared__ int sb[64];
    int t = threadIdx.x;
    int i = blockIdx.x * SCAN_B + t;
    if (t < 64) sb[t] = (t < SCAN_NB && t < (int)blockIdx.x) ? g_bsum[t] : 0;
    int v = (i < N_NODES) ? g_deg[i] : 0;
    s[t] = v;
    __syncthreads();
    // reduce sb[0..63] -> sb[0]
    if (t < 32) sb[t] += sb[t + 32];
    __syncthreads();
    if (t < 16) sb[t] += sb[t + 16];
    __syncthreads();
    if (t < 8) sb[t] += sb[t + 8];
    __syncthreads();
    if (t < 4) sb[t] += sb[t + 4];
    __syncthreads();
    if (t < 2) sb[t] += sb[t + 2];
    __syncthreads();
    if (t < 1) sb[t] += sb[t + 1];
    __syncthreads();
    int boff = sb[0];
    // inclusive scan within block
    for (int off = 1; off < SCAN_B; off <<= 1) {
        int x = (t >= off) ? s[t - off] : 0;
        __syncthreads();
        s[t] += x;
        __syncthreads();
    }
    if (i < N_NODES) {
        int o = boff + s[t] - v;  // exclusive
        g_off[i] = o;
        g_cur[i] = o;
    }
}

__global__ void fill_kernel() {
    int i = blockIdx.x * blockDim.x + threadIdx.x;
    if (i < N_EDGES) {
        int p = atomicAdd(&g_cur[g_dst[i]], 1);
        g_csr[p] = g_src[i];
    }
}

// ---------------- dual GEMM, packed f32x2 FMA: yl = in@Wl, yr = in@Wr + b -----
// BM=128, BN=64, BK=16, 256 threads, thread tile 8x4 (x2 outputs).
// Accumulators held as f32x2 pairs -> half the FMA instruction count;
// packs/splats issue on the alu pipe and overlap the fma pipe.
__global__ __launch_bounds__(256)
void gemm_dual(const float* __restrict__ xin, int in_id,
               const float* __restrict__ Wl,
               const float* __restrict__ bias, const float* __restrict__ Wr,
               int K) {
    const float* in = (in_id < 0) ? xin : buf_by_id(in_id);
    const int M = N_NODES;

    __shared__ float sA[16][128];
    __shared__ float sBl[16][64];
    __shared__ float sBr[16][64];

    int tid = threadIdx.x;
    int tx = tid & 15;
    int ty = tid >> 4;
    int tx4 = tx * 4;
    int ty8 = ty * 8;
    int rowBase = blockIdx.x * 128;

    unsigned long long aL[8][2];
    unsigned long long aR[8][2];
#pragma unroll
    for (int i = 0; i < 8; i++) {
        aL[i][0] = 0ULL; aL[i][1] = 0ULL;
        aR[i][0] = 0ULL; aR[i][1] = 0ULL;
    }

    for (int k0 = 0; k0 < K; k0 += 16) {
#pragma unroll
        for (int l = 0; l < 2; l++) {
            int li = tid + l * 256;
            int nl = li >> 2;
            int kq = li & 3;
            int node = rowBase + nl;
            float4 v = make_float4(0.f, 0.f, 0.f, 0.f);
            if (node < M) v = *(const float4*)(in + (size_t)node * K + k0 + kq * 4);
            sA[kq * 4 + 0][nl] = v.x;
            sA[kq * 4 + 1][nl] = v.y;
            sA[kq * 4 + 2][nl] = v.z;
            sA[kq * 4 + 3][nl] = v.w;
        }
        {
            int kk = tid >> 4;
            int jq = tid & 15;
            float4 vl = *(const float4*)(Wl + (size_t)(k0 + kk) * 64 + jq * 4);
            float4 vr = *(const float4*)(Wr + (size_t)(k0 + kk) * 64 + jq * 4);
            *(float4*)&sBl[kk][jq * 4] = vl;
            *(float4*)&sBr[kk][jq * 4] = vr;
        }
        __syncthreads();

#pragma unroll
        for (int kk = 0; kk < 16; kk++) {
            float4 a0 = *(const float4*)&sA[kk][ty8];
            float4 a1 = *(const float4*)&sA[kk][ty8 + 4];
            float4 b0 = *(const float4*)&sBl[kk][tx4];
            float4 c0 = *(const float4*)&sBr[kk][tx4];
            unsigned long long bl0 = pk2(b0.x, b0.y);
            unsigned long long bl1 = pk2(b0.z, b0.w);
            unsigned long long br0 = pk2(c0.x, c0.y);
            unsigned long long br1 = pk2(c0.z, c0.w);
            float a[8] = {a0.x, a0.y, a0.z, a0.w, a1.x, a1.y, a1.z, a1.w};
#pragma unroll
            for (int i = 0; i < 8; i++) {
                unsigned long long ai = spl2(a[i]);
                fma2(aL[i][0], ai, bl0);
                fma2(aL[i][1], ai, bl1);
                fma2(aR[i][0], ai, br0);
                fma2(aR[i][1], ai, br1);
            }
        }
        __syncthreads();
    }

    float4 bb = *(const float4*)(bias + tx4);
#pragma unroll
    for (int i = 0; i < 8; i++) {
        int node = rowBase + ty8 + i;
        if (node < M) {
            float2 l0 = upk2(aL[i][0]);
            float2 l1 = upk2(aL[i][1]);
            float2 r0 = upk2(aR[i][0]);
            float2 r1 = upk2(aR[i][1]);
            float4 ol = make_float4(l0.x, l0.y, l1.x, l1.y);
            float4 orr = make_float4(r0.x + bb.x, r0.y + bb.y,
                                     r1.x + bb.z, r1.y + bb.w);
            *(float4*)(g_yl + (size_t)node * 64 + tx4) = ol;
            *(float4*)(g_yr + (size_t)node * 64 + tx4) = orr;
        }
    }
}

// ---------------- aggregation: out[n] = mean_{e in CSR(n)} yl[src_e] + yr[n] ----
// Half-warp (16 lanes) per node, float4 per lane, edge loop unrolled x4.
__global__ __launch_bounds__(256)
void aggregate_kernel(int out_id) {
    float* out = buf_by_id(out_id);
    int tid = blockIdx.x * blockDim.x + threadIdx.x;
    int node = tid >> 4;             // 16 threads per node
    int lane = threadIdx.x & 15;     // covers 64 floats as float4
    if (node >= N_NODES) return;
    int start = g_off[node];
    int d = g_deg[node];

    float4 a = make_float4(0.f, 0.f, 0.f, 0.f);
    const int* csr = g_csr + start;
    int e = 0;
    for (; e + 4 <= d; e += 4) {
        int s0 = csr[e + 0];
        int s1 = csr[e + 1];
        int s2 = csr[e + 2];
        int s3 = csr[e + 3];
        float4 v0 = *(const float4*)(g_yl + (size_t)s0 * 64 + lane * 4);
        float4 v1 = *(const float4*)(g_yl + (size_t)s1 * 64 + lane * 4);
        float4 v2 = *(const float4*)(g_yl + (size_t)s2 * 64 + lane * 4);
        float4 v3 = *(const float4*)(g_yl + (size_t)s3 * 64 + lane * 4);
        a.x += v0.x + v1.x + v2.x + v3.x;
        a.y += v0.y + v1.y + v2.y + v3.y;
        a.z += v0.z + v1.z + v2.z + v3.z;
        a.w += v0.w + v1.w + v2.w + v3.w;
    }
    for (; e < d; e++) {
        int s = csr[e];
        float4 v = *(const float4*)(g_yl + (size_t)s * 64 + lane * 4);
        a.x += v.x; a.y += v.y; a.z += v.z; a.w += v.w;
    }
    float inv = (d > 0) ? (1.0f / (float)d) : 0.0f;
    float4 r = *(const float4*)(g_yr + (size_t)node * 64 + lane * 4);
    float4 o;
    o.x = a.x * inv + r.x;
    o.y = a.y * inv + r.y;
    o.z = a.z * inv + r.z;
    o.w = a.w * inv + r.w;
    *(float4*)(out + (size_t)node * 64 + lane * 4) = o;
}

// ---------------- global mean pool (batch sorted) ----------------
__global__ void pool_kernel(int in_id) {
    const float* h = buf_by_id(in_id);
    int f = threadIdx.x & 63;
    int sub = threadIdx.x >> 6;
    int base = blockIdx.x * 128 + sub * 32;
    if (base >= N_NODES) return;
    int end = base + 32;
    if (end > N_NODES) end = N_NODES;
    float run = 0.0f, cnt = 0.0f;
    int cur = -1;
    for (int n = base; n < end; n++) {
        int b = g_batch[n];
        if (b != cur) {
            if (cur >= 0) {
                atomicAdd(&g_pool[cur * 64 + f], run);
                if (f == 0) atomicAdd(&g_pcnt[cur], cnt);
            }
            run = 0.0f; cnt = 0.0f; cur = b;
        }
        run += h[(size_t)n * 64 + f];
        cnt += 1.0f;
    }
    if (cur >= 0) {
        atomicAdd(&g_pool[cur * 64 + f], run);
        if (f == 0) atomicAdd(&g_pcnt[cur], cnt);
    }
}

// ---------------- MLP head ----------------
__global__ void mlp_gemm(int stage, const float* __restrict__ W,
                         const float* __restrict__ b, float* __restrict__ ext_out,
                         int K, int Nout) {
    const float* in;
    float* out;
    switch (stage) {
        case 0: in = g_pool; out = g_m1; break;
        case 1: in = g_m1;   out = g_m2; break;
        case 2: in = g_m2;   out = g_m3; break;
        default: in = g_m3;  out = ext_out; break;
    }
    int idx = blockIdx.x * blockDim.x + threadIdx.x;
    if (idx >= NUM_GRAPHS * Nout) return;
    int r = idx / Nout;
    int j = idx - r * Nout;
    float acc = 0.0f;
    const float* ir = in + (size_t)r * K;
    for (int k = 0; k < K; k++) acc += ir[k] * W[(size_t)k * Nout + j];
    if (stage == 0) acc *= 1.0f / fmaxf(g_pcnt[r], 1.0f);
    out[idx] = acc + b[j];
}

// one block per column; blockDim = NUM_GRAPHS = 256
__global__ void bn_tanh_kernel(int which, const float* __restrict__ g,
                               const float* __restrict__ be, int ncols) {
    float* y = (which == 0) ? g_m1 : (which == 1) ? g_m2 : g_m3;
    __shared__ float sd[256];
    __shared__ float sm[2];
    int j = blockIdx.x;
    int t = threadIdx.x;
    float v = y[(size_t)t * ncols + j];
    sd[t] = v;
    __syncthreads();
    for (int s = 128; s > 0; s >>= 1) {
        if (t < s) sd[t] += sd[t + s];
        __syncthreads();
    }
    if (t == 0) sm[0] = sd[0] * (1.0f / NUM_GRAPHS);
    __syncthreads();
    float mean = sm[0];
    float d = v - mean;
    sd[t] = d * d;
    __syncthreads();
    for (int s = 128; s > 0; s >>= 1) {
        if (t < s) sd[t] += sd[t + s];
        __syncthreads();
    }
    if (t == 0) sm[1] = sd[0] * (1.0f / NUM_GRAPHS);
    __syncthreads();
    float var = sm[1];
    float o = d * rsqrtf(var + EPS) * g[j] + be[j];
    y[(size_t)t * ncols + j] = tanhf(o);
}

// ---------------- launch ----------------
extern "C" void kernel_launch(void* const* d_in, const int* in_sizes, int n_in,
                              void* d_out, int out_size) {
    const float* x     = (const float*)d_in[0];
    const void*  eidx  = d_in[1];
    const void*  batch = d_in[2];
    const float* W1l = (const float*)d_in[3];
    const float* b1l = (const float*)d_in[4];
    const float* W1r = (const float*)d_in[5];
    const float* W2l = (const float*)d_in[6];
    const float* b2l = (const float*)d_in[7];
    const float* W2r = (const float*)d_in[8];
    const float* W3l = (const float*)d_in[9];
    const float* b3l = (const float*)d_in[10];
    const float* W3r = (const float*)d_in[11];
    const float* lin1_w = (const float*)d_in[12];
    const float* lin1_b = (const float*)d_in[13];
    const float* g1  = (const float*)d_in[14];
    const float* be1 = (const float*)d_in[15];
    const float* lin2_w = (const float*)d_in[16];
    const float* lin2_b = (const float*)d_in[17];
    const float* g2  = (const float*)d_in[18];
    const float* be2 = (const float*)d_in[19];
    const float* lin3_w = (const float*)d_in[20];
    const float* lin3_b = (const float*)d_in[21];
    const float* g3  = (const float*)d_in[22];
    const float* be3 = (const float*)d_in[23];
    const float* lin4_w = (const float*)d_in[24];
    const float* lin4_b = (const float*)d_in[25];
    float* out = (float*)d_out;

    const int EB = (N_EDGES + 255) / 256;        // 3125
    const int NBn = (N_NODES + 255) / 256;       // 196
    const int GB = (N_NODES + 127) / 128;        // 391 (128 rows per block)
    const int AB = (N_NODES * 16 + 255) / 256;   // 3125 (16 threads/node)

    // zero BEFORE convert (fused degree histogram)
    zero_kernel<<<NBn, 256>>>();
    convert_edges<<<EB, 256>>>(eidx);
    convert_batch<<<NBn, 256>>>(batch, eidx);

    // CSR build (blocksum + fused scan)
    blocksum_kernel<<<SCAN_NB, SCAN_B>>>();
    block_scan_kernel<<<SCAN_NB, SCAN_B>>>();
    fill_kernel<<<EB, 256>>>();

    // Layer 1: linear-first, then aggregate (hA = buf 2, hB = buf 3)
    gemm_dual<<<GB, 256>>>(x, -1, W1l, b1l, W1r, IN_DIM);
    aggregate_kernel<<<AB, 256>>>(2);
    // Layer 2
    gemm_dual<<<GB, 256>>>(nullptr, 2, W2l, b2l, W2r, H_DIM);
    aggregate_kernel<<<AB, 256>>>(3);
    // Layer 3
    gemm_dual<<<GB, 256>>>(nullptr, 3, W3l, b3l, W3r, H_DIM);
    aggregate_kernel<<<AB, 256>>>(2);

    // global mean pool (division folded into mlp stage 0)
    pool_kernel<<<GB, 256>>>(2);

    // MLP head
    mlp_gemm<<<(NUM_GRAPHS * HID + 255) / 256, 256>>>(0, lin1_w, lin1_b, nullptr,
                                                      H_DIM, HID);
    bn_tanh_kernel<<<HID, 256>>>(0, g1, be1, HID);
    mlp_gemm<<<(NUM_GRAPHS * (HID / 2) + 255) / 256, 256>>>(1, lin2_w, lin2_b, nullptr,
                                                            HID, HID / 2);
    bn_tanh_kernel<<<HID / 2, 256>>>(1, g2, be2, HID / 2);
    mlp_gemm<<<(NUM_GRAPHS * (HID / 4) + 255) / 256, 256>>>(2, lin3_w, lin3_b, nullptr,
                                                            HID / 2, HID / 4);
    bn_tanh_kernel<<<HID / 4, 256>>>(2, g3, be3, HID / 4);
    mlp_gemm<<<(NUM_GRAPHS * 10 + 255) / 256, 256>>>(3, lin4_w, lin4_b, out,
                                                     HID / 4, 10);
}